// round 9
// baseline (speedup 1.0000x reference)
#include <cuda_runtime.h>

// ---------------- problem constants ----------------
#define SEQ     256
#define BATCH   128
#define HID     256
#define NLAYERS 12
#define NOUT    10

// scan geometry: 128 blocks = 16 unit-groups x 8 batch-groups, persistent
#define NBLK         128
#define SCAN_THREADS 256
#define BB           16            // batch rows per block
#define UB           16            // hidden units per block (=> 64 gate cols)
#define APITCH       514           // duplicated x/h tile row pitch (floats)
#define GPAD         66            // partial-buffer row pitch

// smem layout (float offsets)
#define SM_W    0                          // fused W|U slice [512][64]
#define SM_X    (SM_W + 512*64)            // x tile dup  [16][514]
#define SM_H    (SM_X + BB*APITCH)         // h tile dup  [16][514]
#define SM_G    (SM_H + BB*APITCH)         // 8 partial tiles [16][66]
#define SM_TOT  (SM_G + 8*BB*GPAD)         // 57664 floats = 230656 bytes

typedef unsigned long long ull;

// ---------------- device scratch (no allocations allowed) ----------------
__device__ float    g_seq[2][(size_t)SEQ * BATCH * HID]; // ping-pong layer sequences
__device__ float    g_h[2][BATCH][HID];                  // ping-pong hidden state
__device__ unsigned g_count;                             // grid-barrier ticket counter

// ---------------- packed f32x2 + barrier helpers ----------------
__device__ __forceinline__ ull fma2(ull a, ull b, ull c) {
    ull d;
    asm("fma.rn.f32x2 %0, %1, %2, %3;" : "=l"(d) : "l"(a), "l"(b), "l"(c));
    return d;
}
__device__ __forceinline__ ull pack2(float v) {
    ull d;
    asm("mov.b64 %0, {%1, %1};" : "=l"(d) : "f"(v));
    return d;
}
__device__ __forceinline__ void bar_arrive(unsigned* p) {
    asm volatile("red.release.gpu.add.u32 [%0], %1;" :: "l"(p), "r"(1u) : "memory");
}
__device__ __forceinline__ unsigned ld_acq(const unsigned* p) {
    unsigned v;
    asm volatile("ld.acquire.gpu.u32 %0, [%1];" : "=r"(v) : "l"(p) : "memory");
    return v;
}

// ---------------- math helpers ----------------
__device__ __forceinline__ float sigf(float x) {
    return 1.0f / (1.0f + __expf(-x));
}
__device__ __forceinline__ float tanh_sig(float x) {
    return fmaf(2.0f, sigf(2.0f * x), -1.0f);   // tanh(x) = 2*sigmoid(2x) - 1
}

// ---------------- init: reset barrier counter (deterministic per replay) ----------------
__global__ void init_state_kernel() {
    if (threadIdx.x == 0 && blockIdx.x == 0) g_count = 0u;
}

// ---------------- embedding gather -> g_seq[0] laid out [s][b][e] ----------------
__global__ void embed_kernel(const int* __restrict__ x, const float* __restrict__ tab) {
    int idx = blockIdx.x * blockDim.x + threadIdx.x;     // over S*B*64 float4 chunks
    if (idx >= BATCH * SEQ * (HID / 4)) return;
    int e4 = idx & 63;
    int sb = idx >> 6;            // s*BATCH + b
    int b  = sb & (BATCH - 1);
    int s  = sb >> 7;
    int tok = x[b * SEQ + s];
    float4 v = *(const float4*)(tab + (size_t)tok * HID + e4 * 4);
    *(float4*)(&g_seq[0][(size_t)sb * HID + e4 * 4]) = v;
}

// ---------------- block helpers (all-thread cooperative) ----------------
// Load fused weight slice [512 rows][64 gate cols] for this block's unit group.
__device__ __forceinline__ void load_wslice(float* Wsm, const float* W,
                                            const float* U, int kh0) {
    for (int idx = threadIdx.x; idx < 512 * 16; idx += SCAN_THREADS) {
        int k = idx >> 4;
        int c = idx & 15;
        int gate = c >> 2;
        int u4   = (c & 3) << 2;
        const float* src = (k < 256) ? (W + (size_t)k * 1024)
                                     : (U + (size_t)(k - 256) * 1024);
        float4 v = *(const float4*)(src + gate * 256 + kh0 + u4);
        *(float4*)(Wsm + k * 64 + gate * 16 + u4) = v;
    }
}

// Stage a 16x256 tile into duplicated {v,v} layout (pitch APITCH).
template <bool BYPASS>
__device__ __forceinline__ void stage_dup(float* dst, const float* src) {
    for (int idx = threadIdx.x; idx < BB * (HID / 2); idx += SCAN_THREADS) {
        int r  = idx >> 7;
        int c2 = idx & 127;
        float2 v = BYPASS ? __ldcg(((const float2*)(src + r * HID)) + c2)
                          : ((const float2*)(src + r * HID))[c2];
        ull* d = (ull*)(dst + r * APITCH) + 2 * c2;
        d[0] = pack2(v.x);
        d[1] = pack2(v.y);
    }
}

__device__ __forceinline__ void stage_zero(float* dst) {
    for (int idx = threadIdx.x; idx < BB * (HID / 2); idx += SCAN_THREADS) {
        int r  = idx >> 7;
        int c2 = idx & 127;
        ull* d = (ull*)(dst + r * APITCH) + 2 * c2;
        d[0] = 0ull;
        d[1] = 0ull;
    }
}

// ---------------- persistent 12-layer LSTM scan ----------------
// Block (bx, by): hidden units [bx*16,+16), batch rows [by*16,+16).
// 8 warps, warp w owns K chunk [w*64,+64) of fused K=512 (x|h),
// computing the 16x64 gate-partial tile with R4xC8 f32x2 register blocking.
__global__ void __launch_bounds__(SCAN_THREADS, 1)
scan_all_kernel(const float* __restrict__ W0, const float* __restrict__ U0,
                const float* __restrict__ b0,
                const float* __restrict__ Ws, const float* __restrict__ Us,
                const float* __restrict__ bs)
{
    extern __shared__ float sm[];
    float* Wsm = sm + SM_W;
    float* xsm = sm + SM_X;
    float* hsm = sm + SM_H;
    float* gsm = sm + SM_G;

    const int tid = threadIdx.x;
    const int kh0 = blockIdx.x * UB;   // first hidden unit owned
    const int b0r = blockIdx.y * BB;   // first batch row owned

    // ---- gate-phase mapping ----
    const int gr = tid >> 4;          // local batch row 0..15
    const int gu = tid & 15;          // local hidden unit 0..15
    const int hb = b0r + gr;
    const int hu = kh0 + gu;
    float creg = 0.0f;                // cell state lives in a register for all 12 layers
    float bi = b0[hu];
    float bf = b0[256 + hu];
    float bg = b0[512 + hu];
    float bo = b0[768 + hu];

    // ---- matmul mapping: warp -> K chunk, lane -> (row group, col group) ----
    const int w  = tid >> 5;           // 0..7
    const int ln = tid & 31;
    const int rg = ln >> 3;            // rows 4*rg .. 4*rg+3
    const int cg = ln & 7;             // col pairs {2*cg + 16*j}
    const ull* Apane = (const ull*)((w < 4) ? xsm : hsm);
    const int  koff  = (w & 3) * 64;   // ull offset of warp's K chunk within pane row
    const ull* wbase = (const ull*)(Wsm + (size_t)(w * 64) * 64) + cg;
    float*     gout  = gsm + w * (BB * GPAD);

    const float* xin  = g_seq[0];
    float*       yout = g_seq[1];

    // ---- prologue: layer-0 weights, x_0, h_0 = 0 ----
    load_wslice(Wsm, W0, U0, kh0);
    stage_dup<false>(xsm, xin + (size_t)b0r * HID);
    stage_zero(hsm);
    __syncthreads();

    unsigned barn = 0;                 // barriers completed so far (same in all blocks)

    for (int l = 0; l < NLAYERS; ++l) {
        for (int t = 0; t < SEQ; ++t) {
            // ---- K-chunk matmul: 4 rows x 8 cols per thread, f32x2 ----
            {
                const ull* a0 = Apane + (4 * rg + 0) * (APITCH / 2) + koff;
                const ull* a1 = a0 + (APITCH / 2);
                const ull* a2 = a1 + (APITCH / 2);
                const ull* a3 = a2 + (APITCH / 2);
                ull acc[4][4];
                #pragma unroll
                for (int r = 0; r < 4; ++r)
                    #pragma unroll
                    for (int j = 0; j < 4; ++j)
                        acc[r][j] = 0ull;

                #pragma unroll 8
                for (int kk = 0; kk < 64; ++kk) {
                    const ull* wr = wbase + kk * 32;
                    ull w0 = wr[0];
                    ull w1 = wr[8];
                    ull w2 = wr[16];
                    ull w3 = wr[24];
                    ull v;
                    v = a0[kk];
                    acc[0][0] = fma2(v, w0, acc[0][0]);
                    acc[0][1] = fma2(v, w1, acc[0][1]);
                    acc[0][2] = fma2(v, w2, acc[0][2]);
                    acc[0][3] = fma2(v, w3, acc[0][3]);
                    v = a1[kk];
                    acc[1][0] = fma2(v, w0, acc[1][0]);
                    acc[1][1] = fma2(v, w1, acc[1][1]);
                    acc[1][2] = fma2(v, w2, acc[1][2]);
                    acc[1][3] = fma2(v, w3, acc[1][3]);
                    v = a2[kk];
                    acc[2][0] = fma2(v, w0, acc[2][0]);
                    acc[2][1] = fma2(v, w1, acc[2][1]);
                    acc[2][2] = fma2(v, w2, acc[2][2]);
                    acc[2][3] = fma2(v, w3, acc[2][3]);
                    v = a3[kk];
                    acc[3][0] = fma2(v, w0, acc[3][0]);
                    acc[3][1] = fma2(v, w1, acc[3][1]);
                    acc[3][2] = fma2(v, w2, acc[3][2]);
                    acc[3][3] = fma2(v, w3, acc[3][3]);
                }

                #pragma unroll
                for (int r = 0; r < 4; ++r) {
                    float* orow = gout + (4 * rg + r) * GPAD + 2 * cg;
                    #pragma unroll
                    for (int j = 0; j < 4; ++j)
                        *(ull*)(orow + 16 * j) = acc[r][j];
                }
            }
            __syncthreads();

            // ---- gate nonlinearity + state update (c stays in register) ----
            {
                float s0 = bi, s1 = bf, s2 = bg, s3 = bo;
                #pragma unroll
                for (int ww = 0; ww < 8; ++ww) {
                    const float* gp = gsm + ww * (BB * GPAD) + gr * GPAD;
                    s0 += gp[gu];
                    s1 += gp[16 + gu];
                    s2 += gp[32 + gu];
                    s3 += gp[48 + gu];
                }
                float ct = sigf(s1) * creg + sigf(s0) * tanh_sig(s2);
                float hv = sigf(s3) * tanh_sig(ct);
                creg = ct;
                __stcg(&g_h[(t + 1) & 1][hb][hu], hv);           // broadcast state (L2)
                yout[((size_t)t * BATCH + hb) * HID + hu] = hv;  // layer output sequence
            }

            if (l == NLAYERS - 1 && t == SEQ - 1) break;

            // ---- grid barrier (release/acquire), staging overlapped ----
            __syncthreads();                       // block's h stores + gsm reads done
            if (tid == 0) bar_arrive(&g_count);    // fire-and-forget release
            ++barn;
            const unsigned tgt = barn * NBLK;

            if (t < SEQ - 1) {
                // next step's x (no cross-block dependency)
                stage_dup<false>(xsm, xin + ((size_t)(t + 1) * BATCH + b0r) * HID);
            } else {
                // layer boundary: shared weights load only once (l==0 -> l==1)
                if (l == 0) {
                    load_wslice(Wsm, Ws, Us, kh0);
                    bi = bs[hu];
                    bf = bs[256 + hu];
                    bg = bs[512 + hu];
                    bo = bs[768 + hu];
                }
                // next layer's x_0 = this layer's output at t=0 (long since visible)
                stage_dup<false>(xsm, yout + (size_t)b0r * HID);
            }

            while (ld_acq(&g_count) < tgt) { }     // every thread acquires

            // h_{t+1} (produced by other SMs) -> duplicated smem pane
            stage_dup<true>(hsm, &g_h[(t + 1) & 1][b0r][0]);
            __syncthreads();
        }
        // swap sequence buffers for next layer
        const float* tx = xin;
        xin  = yout;
        yout = (float*)tx;
    }
}

// ---------------- final FC: out[b][o] = h_final[b] . fcW[:,o] + fcb[o] ----------------
__global__ void fc_kernel(const float* __restrict__ fcW,
                          const float* __restrict__ fcb,
                          float* __restrict__ out)
{
    int idx = blockIdx.x * blockDim.x + threadIdx.x;
    if (idx >= BATCH * NOUT) return;
    int b = idx / NOUT;
    int o = idx - b * NOUT;
    float acc = fcb[o];
    const float* hrow = &g_h[0][b][0];   // t=255 writes parity (255+1)&1 = buf 0
    #pragma unroll 8
    for (int k = 0; k < HID; ++k)
        acc = fmaf(hrow[k], fcW[k * NOUT + o], acc);
    out[idx] = acc;
}

// ---------------- launch ----------------
extern "C" void kernel_launch(void* const* d_in, const int* in_sizes, int n_in,
                              void* d_out, int out_size)
{
    const int*   x   = (const int*)  d_in[0];
    const float* tab = (const float*)d_in[1];
    const float* W0  = (const float*)d_in[2];
    const float* U0  = (const float*)d_in[3];
    const float* b0  = (const float*)d_in[4];
    const float* Ws  = (const float*)d_in[5];
    const float* Us  = (const float*)d_in[6];
    const float* bs  = (const float*)d_in[7];
    const float* fcW = (const float*)d_in[8];
    const float* fcb = (const float*)d_in[9];
    float* out = (float*)d_out;

    cudaFuncSetAttribute(scan_all_kernel,
                         cudaFuncAttributeMaxDynamicSharedMemorySize,
                         SM_TOT * (int)sizeof(float));

    init_state_kernel<<<1, 32>>>();     // reset barrier counter per replay

    embed_kernel<<<(BATCH * SEQ * (HID / 4) + 255) / 256, 256>>>(x, tab);

    scan_all_kernel<<<dim3(16, 8), SCAN_THREADS, SM_TOT * (int)sizeof(float)>>>(
        W0, U0, b0, Ws, Us, bs);

    fc_kernel<<<(BATCH * NOUT + 255) / 256, 256>>>(fcW, fcb, out);

    (void)in_sizes; (void)n_in; (void)out_size;
}

// round 10
// speedup vs baseline: 1.2208x; 1.2208x over previous
#include <cuda_runtime.h>

// ---------------- problem constants ----------------
#define SEQ     256
#define BATCH   128
#define HID     256
#define NLAYERS 12
#define NOUT    10

// scan geometry: 128 blocks = 16 unit-groups x 8 batch-groups, persistent
#define SCAN_THREADS 256
#define BB           16            // batch rows per block
#define UB           16            // hidden units per block (=> 64 gate cols)
#define NSYNC        16            // blocks per barrier group (one per by)
#define APITCH       260           // x/h tile row pitch (floats, 16B-aligned rows)
#define GPAD         68            // partial-buffer row pitch (16B-aligned)

// smem layout (float offsets)
#define SM_W    0                          // fused W|U slice [512][64]
#define SM_X    (SM_W + 512*64)            // x tile [16][260]
#define SM_H    (SM_X + BB*APITCH)         // h tile [16][260]
#define SM_G    (SM_H + BB*APITCH)         // 8 partial tiles [16][68]
#define SM_TOT  (SM_G + 8*BB*GPAD)         // 49792 floats = 199168 bytes

typedef unsigned long long ull;

// ---------------- device scratch (no allocations allowed) ----------------
__device__ float    g_seq[2][(size_t)SEQ * BATCH * HID]; // ping-pong layer sequences
__device__ float    g_h[2][BATCH][HID];                  // ping-pong hidden state
__device__ unsigned g_cnt[8][128];                       // per-by barrier counters (512B apart)

// ---------------- packed f32x2 + barrier helpers ----------------
__device__ __forceinline__ ull fma2(ull a, ull b, ull c) {
    ull d;
    asm("fma.rn.f32x2 %0, %1, %2, %3;" : "=l"(d) : "l"(a), "l"(b), "l"(c));
    return d;
}
__device__ __forceinline__ ull pack2(float v) {
    ull d;
    asm("mov.b64 %0, {%1, %1};" : "=l"(d) : "f"(v));
    return d;
}
__device__ __forceinline__ void bar_arrive(unsigned* p) {
    asm volatile("red.release.gpu.add.u32 [%0], %1;" :: "l"(p), "r"(1u) : "memory");
}
__device__ __forceinline__ unsigned ld_acq(const unsigned* p) {
    unsigned v;
    asm volatile("ld.acquire.gpu.u32 %0, [%1];" : "=r"(v) : "l"(p) : "memory");
    return v;
}

// ---------------- math helpers ----------------
__device__ __forceinline__ float sigf(float x) {
    return 1.0f / (1.0f + __expf(-x));
}
__device__ __forceinline__ float tanh_sig(float x) {
    return fmaf(2.0f, sigf(2.0f * x), -1.0f);   // tanh(x) = 2*sigmoid(2x) - 1
}

// ---------------- init: reset barrier counters (deterministic per replay) ----------------
__global__ void init_state_kernel() {
    int i = threadIdx.x;
    if (i < 8) g_cnt[i][0] = 0u;
}

// ---------------- embedding gather -> g_seq[0] laid out [s][b][e] ----------------
__global__ void embed_kernel(const int* __restrict__ x, const float* __restrict__ tab) {
    int idx = blockIdx.x * blockDim.x + threadIdx.x;     // over S*B*64 float4 chunks
    if (idx >= BATCH * SEQ * (HID / 4)) return;
    int e4 = idx & 63;
    int sb = idx >> 6;            // s*BATCH + b
    int b  = sb & (BATCH - 1);
    int s  = sb >> 7;
    int tok = x[b * SEQ + s];
    float4 v = *(const float4*)(tab + (size_t)tok * HID + e4 * 4);
    *(float4*)(&g_seq[0][(size_t)sb * HID + e4 * 4]) = v;
}

// ---------------- block helpers (all-thread cooperative) ----------------
// Load fused weight slice [512 rows][64 gate cols] for this block's unit group.
__device__ __forceinline__ void load_wslice(float* Wsm, const float* W,
                                            const float* U, int kh0) {
    for (int idx = threadIdx.x; idx < 512 * 16; idx += SCAN_THREADS) {
        int k = idx >> 4;
        int c = idx & 15;
        int gate = c >> 2;
        int u4   = (c & 3) << 2;
        const float* src = (k < 256) ? (W + (size_t)k * 1024)
                                     : (U + (size_t)(k - 256) * 1024);
        float4 v = *(const float4*)(src + gate * 256 + kh0 + u4);
        *(float4*)(Wsm + k * 64 + gate * 16 + u4) = v;
    }
}

// Stage a 16x256 tile into smem (pitch APITCH), optionally L1-bypass.
template <bool BYPASS>
__device__ __forceinline__ void stage(float* dst, const float* src) {
    for (int idx = threadIdx.x; idx < BB * (HID / 2); idx += SCAN_THREADS) {
        int r  = idx >> 7;
        int c2 = idx & 127;
        float2 v = BYPASS ? __ldcg(((const float2*)(src + r * HID)) + c2)
                          : ((const float2*)(src + r * HID))[c2];
        ((float2*)(dst + r * APITCH))[c2] = v;
    }
}

__device__ __forceinline__ void stage_zero(float* dst) {
    for (int idx = threadIdx.x; idx < BB * (HID / 2); idx += SCAN_THREADS) {
        int r  = idx >> 7;
        int c2 = idx & 127;
        ((float2*)(dst + r * APITCH))[c2] = make_float2(0.f, 0.f);
    }
}

// ---------------- persistent 12-layer LSTM scan ----------------
// Block (bx, by): hidden units [bx*16,+16), batch rows [by*16,+16).
// All data dependencies stay within a by-group -> barrier spans only 16 blocks.
// 8 warps, warp w owns K chunk [w*64,+64) of fused K=512 (x|h); lane (rg,cg)
// computes rows {rg,rg+4,rg+8,rg+12} x cols {4cg..4cg+3, 32+4cg..32+4cg+3}.
__global__ void __launch_bounds__(SCAN_THREADS, 1)
scan_all_kernel(const float* __restrict__ W0, const float* __restrict__ U0,
                const float* __restrict__ b0,
                const float* __restrict__ Ws, const float* __restrict__ Us,
                const float* __restrict__ bs)
{
    extern __shared__ float sm[];
    float* Wsm = sm + SM_W;
    float* xsm = sm + SM_X;
    float* hsm = sm + SM_H;
    float* gsm = sm + SM_G;

    const int tid = threadIdx.x;
    const int kh0 = blockIdx.x * UB;   // first hidden unit owned
    const int by  = blockIdx.y;
    const int b0r = by * BB;           // first batch row owned
    unsigned* cnt = &g_cnt[by][0];

    // ---- gate-phase mapping ----
    const int gr = tid >> 4;          // local batch row 0..15
    const int gu = tid & 15;          // local hidden unit 0..15
    const int hb = b0r + gr;
    const int hu = kh0 + gu;
    float creg = 0.0f;                // cell state in a register for all 12 layers
    float bi = b0[hu];
    float bf = b0[256 + hu];
    float bg = b0[512 + hu];
    float bo = b0[768 + hu];

    // ---- matmul mapping ----
    const int w  = tid >> 5;           // 0..7
    const int ln = tid & 31;
    const int rg = ln >> 3;            // rows rg + 4q
    const int cg = ln & 7;             // col quads 4cg, 32+4cg
    const float* Apane = (w < 4) ? xsm : hsm;
    const int    k0    = (w & 3) * 64;
    const float* wbase = Wsm + (size_t)(w * 64) * 64 + 4 * cg;
    float*       gout  = gsm + w * (BB * GPAD);

    const float* xin  = g_seq[0];
    float*       yout = g_seq[1];

    // ---- prologue: layer-0 weights, x_0, h_0 = 0 ----
    load_wslice(Wsm, W0, U0, kh0);
    stage<false>(xsm, xin + (size_t)b0r * HID);
    stage_zero(hsm);
    __syncthreads();

    unsigned barn = 0;                 // barriers completed in this by-group

    for (int l = 0; l < NLAYERS; ++l) {
        for (int t = 0; t < SEQ; ++t) {
            // ---- K-chunk matmul: rows {rg+4q}, col quads {4cg, 32+4cg} ----
            {
                const float* ar0 = Apane + (rg     ) * APITCH + k0;
                const float* ar1 = Apane + (rg +  4) * APITCH + k0;
                const float* ar2 = Apane + (rg +  8) * APITCH + k0;
                const float* ar3 = Apane + (rg + 12) * APITCH + k0;
                ull acc[4][4];
                #pragma unroll
                for (int q = 0; q < 4; ++q)
                    #pragma unroll
                    for (int j = 0; j < 4; ++j)
                        acc[q][j] = 0ull;

                #pragma unroll 4
                for (int kk4 = 0; kk4 < 16; ++kk4) {
                    // one float4 per owned row covers 4 consecutive k values
                    float4 av0 = *(const float4*)(ar0 + kk4 * 4);
                    float4 av1 = *(const float4*)(ar1 + kk4 * 4);
                    float4 av2 = *(const float4*)(ar2 + kk4 * 4);
                    float4 av3 = *(const float4*)(ar3 + kk4 * 4);
                    #pragma unroll
                    for (int s = 0; s < 4; ++s) {
                        const float* wr = wbase + (kk4 * 4 + s) * 64;
                        ulonglong2 wA = *(const ulonglong2*)(wr);       // cols 4cg..+3
                        ulonglong2 wB = *(const ulonglong2*)(wr + 32);  // cols 32+4cg..+3
                        float f0 = (s == 0) ? av0.x : (s == 1) ? av0.y : (s == 2) ? av0.z : av0.w;
                        float f1 = (s == 0) ? av1.x : (s == 1) ? av1.y : (s == 2) ? av1.z : av1.w;
                        float f2 = (s == 0) ? av2.x : (s == 1) ? av2.y : (s == 2) ? av2.z : av2.w;
                        float f3 = (s == 0) ? av3.x : (s == 1) ? av3.y : (s == 2) ? av3.z : av3.w;
                        ull v;
                        v = pack2(f0);
                        acc[0][0] = fma2(v, wA.x, acc[0][0]);
                        acc[0][1] = fma2(v, wA.y, acc[0][1]);
                        acc[0][2] = fma2(v, wB.x, acc[0][2]);
                        acc[0][3] = fma2(v, wB.y, acc[0][3]);
                        v = pack2(f1);
                        acc[1][0] = fma2(v, wA.x, acc[1][0]);
                        acc[1][1] = fma2(v, wA.y, acc[1][1]);
                        acc[1][2] = fma2(v, wB.x, acc[1][2]);
                        acc[1][3] = fma2(v, wB.y, acc[1][3]);
                        v = pack2(f2);
                        acc[2][0] = fma2(v, wA.x, acc[2][0]);
                        acc[2][1] = fma2(v, wA.y, acc[2][1]);
                        acc[2][2] = fma2(v, wB.x, acc[2][2]);
                        acc[2][3] = fma2(v, wB.y, acc[2][3]);
                        v = pack2(f3);
                        acc[3][0] = fma2(v, wA.x, acc[3][0]);
                        acc[3][1] = fma2(v, wA.y, acc[3][1]);
                        acc[3][2] = fma2(v, wB.x, acc[3][2]);
                        acc[3][3] = fma2(v, wB.y, acc[3][3]);
                    }
                }

                #pragma unroll
                for (int q = 0; q < 4; ++q) {
                    float* orow = gout + (rg + 4 * q) * GPAD;
                    *(ulonglong2*)(orow + 4 * cg)      = make_ulonglong2(acc[q][0], acc[q][1]);
                    *(ulonglong2*)(orow + 32 + 4 * cg) = make_ulonglong2(acc[q][2], acc[q][3]);
                }
            }
            __syncthreads();

            // ---- gate nonlinearity + state update (c stays in register) ----
            {
                float s0 = bi, s1 = bf, s2 = bg, s3 = bo;
                #pragma unroll
                for (int ww = 0; ww < 8; ++ww) {
                    const float* gp = gsm + ww * (BB * GPAD) + gr * GPAD;
                    s0 += gp[gu];
                    s1 += gp[16 + gu];
                    s2 += gp[32 + gu];
                    s3 += gp[48 + gu];
                }
                float ct = sigf(s1) * creg + sigf(s0) * tanh_sig(s2);
                float hv = sigf(s3) * tanh_sig(ct);
                creg = ct;
                __stcg(&g_h[(t + 1) & 1][hb][hu], hv);           // by-group broadcast (L2)
                yout[((size_t)t * BATCH + hb) * HID + hu] = hv;  // layer output sequence
            }

            if (l == NLAYERS - 1 && t == SEQ - 1) break;

            // ---- by-group barrier (16 blocks), staging overlapped ----
            __syncthreads();                       // block's h stores + gsm reads done
            if (tid == 0) bar_arrive(cnt);         // fire-and-forget release
            ++barn;
            const unsigned tgt = barn * NSYNC;

            if (t < SEQ - 1) {
                // next step's x (no cross-block dependency)
                stage<false>(xsm, xin + ((size_t)(t + 1) * BATCH + b0r) * HID);
            } else {
                // layer boundary: shared weights loaded only once (l==0 -> l==1)
                if (l == 0) {
                    load_wslice(Wsm, Ws, Us, kh0);
                    bi = bs[hu];
                    bf = bs[256 + hu];
                    bg = bs[512 + hu];
                    bo = bs[768 + hu];
                }
                // next layer's x_0 = this layer's output at t=0 (written by this
                // by-group many barriers ago -> visible)
                stage<false>(xsm, yout + (size_t)b0r * HID);
            }

            if (tid == 0) {
                while (ld_acq(cnt) < tgt) { }      // light poll: 16 pollers/counter... 1 here
            }
            __syncthreads();

            // h_{t+1} (produced by other SMs in this by-group) -> bypass L1
            stage<true>(hsm, &g_h[(t + 1) & 1][b0r][0]);
            __syncthreads();
        }
        // swap sequence buffers for next layer
        const float* tx = xin;
        xin  = yout;
        yout = (float*)tx;
    }
}

// ---------------- final FC: out[b][o] = h_final[b] . fcW[:,o] + fcb[o] ----------------
__global__ void fc_kernel(const float* __restrict__ fcW,
                          const float* __restrict__ fcb,
                          float* __restrict__ out)
{
    int idx = blockIdx.x * blockDim.x + threadIdx.x;
    if (idx >= BATCH * NOUT) return;
    int b = idx / NOUT;
    int o = idx - b * NOUT;
    float acc = fcb[o];
    const float* hrow = &g_h[0][b][0];   // t=255 writes parity (255+1)&1 = buf 0
    #pragma unroll 8
    for (int k = 0; k < HID; ++k)
        acc = fmaf(hrow[k], fcW[k * NOUT + o], acc);
    out[idx] = acc;
}

// ---------------- launch ----------------
extern "C" void kernel_launch(void* const* d_in, const int* in_sizes, int n_in,
                              void* d_out, int out_size)
{
    const int*   x   = (const int*)  d_in[0];
    const float* tab = (const float*)d_in[1];
    const float* W0  = (const float*)d_in[2];
    const float* U0  = (const float*)d_in[3];
    const float* b0  = (const float*)d_in[4];
    const float* Ws  = (const float*)d_in[5];
    const float* Us  = (const float*)d_in[6];
    const float* bs  = (const float*)d_in[7];
    const float* fcW = (const float*)d_in[8];
    const float* fcb = (const float*)d_in[9];
    float* out = (float*)d_out;

    cudaFuncSetAttribute(scan_all_kernel,
                         cudaFuncAttributeMaxDynamicSharedMemorySize,
                         SM_TOT * (int)sizeof(float));

    init_state_kernel<<<1, 32>>>();     // reset barrier counters per replay

    embed_kernel<<<(BATCH * SEQ * (HID / 4) + 255) / 256, 256>>>(x, tab);

    scan_all_kernel<<<dim3(16, 8), SCAN_THREADS, SM_TOT * (int)sizeof(float)>>>(
        W0, U0, b0, Ws, Us, bs);

    fc_kernel<<<(BATCH * NOUT + 255) / 256, 256>>>(fcW, fcb, out);

    (void)in_sizes; (void)n_in; (void)out_size;
}

// round 11
// speedup vs baseline: 1.5201x; 1.2452x over previous
#include <cuda_runtime.h>

// ---------------- problem constants ----------------
#define SEQ     256
#define BATCH   128
#define HID     256
#define NLAYERS 12
#define NOUT    10

// scan geometry: 128 blocks = 16 unit-groups x 8 batch-groups, persistent
#define SCAN_THREADS 256
#define BB           16            // batch rows per block
#define UB           16            // hidden units per block (=> 64 gate cols)
#define NSYNC        16            // blocks per barrier group (one per by)
#define APITCH       260           // x/h tile row pitch (floats, 16B-aligned rows)
#define GPAD         68            // partial-buffer row pitch (16B-aligned)

// smem layout (float offsets)
#define SM_W    0                          // fused W|U slice [512][64]
#define SM_X    (SM_W + 512*64)            // x tile [16][260]
#define SM_H    (SM_X + BB*APITCH)         // h tile [16][260]
#define SM_G    (SM_H + BB*APITCH)         // 8 partial tiles [16][68]
#define SM_TOT  (SM_G + 8*BB*GPAD)         // 49792 floats = 199168 bytes

typedef unsigned long long ull;

// ---------------- device scratch (no allocations allowed) ----------------
__device__ float    g_seq[2][(size_t)SEQ * BATCH * HID]; // ping-pong layer sequences
__device__ float    g_h[2][BATCH][HID];                  // ping-pong hidden state
__device__ unsigned g_cnt[8][128];                       // per-by barrier counters (512B apart)

// ---------------- packed f32x2 + barrier helpers ----------------
__device__ __forceinline__ ull fma2(ull a, ull b, ull c) {
    ull d;
    asm("fma.rn.f32x2 %0, %1, %2, %3;" : "=l"(d) : "l"(a), "l"(b), "l"(c));
    return d;
}
__device__ __forceinline__ ull pack2(float v) {
    ull d;
    asm("mov.b64 %0, {%1, %1};" : "=l"(d) : "f"(v));
    return d;
}
__device__ __forceinline__ void bar_arrive(unsigned* p) {
    asm volatile("red.release.gpu.add.u32 [%0], %1;" :: "l"(p), "r"(1u) : "memory");
}
__device__ __forceinline__ unsigned ld_acq(const unsigned* p) {
    unsigned v;
    asm volatile("ld.acquire.gpu.u32 %0, [%1];" : "=r"(v) : "l"(p) : "memory");
    return v;
}
__device__ __forceinline__ void bar_named(int id) {     // 128-thread named barrier
    asm volatile("bar.sync %0, 128;" :: "r"(id) : "memory");
}

// ---------------- math helpers ----------------
__device__ __forceinline__ float sigf(float x) {
    return 1.0f / (1.0f + __expf(-x));
}
__device__ __forceinline__ float tanh_sig(float x) {
    return fmaf(2.0f, sigf(2.0f * x), -1.0f);   // tanh(x) = 2*sigmoid(2x) - 1
}

// ---------------- init: reset barrier counters (deterministic per replay) ----------------
__global__ void init_state_kernel() {
    int i = threadIdx.x;
    if (i < 8) g_cnt[i][0] = 0u;
}

// ---------------- embedding gather -> g_seq[0] laid out [s][b][e] ----------------
__global__ void embed_kernel(const int* __restrict__ x, const float* __restrict__ tab) {
    int idx = blockIdx.x * blockDim.x + threadIdx.x;     // over S*B*64 float4 chunks
    if (idx >= BATCH * SEQ * (HID / 4)) return;
    int e4 = idx & 63;
    int sb = idx >> 6;            // s*BATCH + b
    int b  = sb & (BATCH - 1);
    int s  = sb >> 7;
    int tok = x[b * SEQ + s];
    float4 v = *(const float4*)(tab + (size_t)tok * HID + e4 * 4);
    *(float4*)(&g_seq[0][(size_t)sb * HID + e4 * 4]) = v;
}

// ---------------- cooperative helpers ----------------
// Full-block weight slice load (prologue): fused [512 rows][64 gate cols].
__device__ __forceinline__ void load_wslice(float* Wsm, const float* W,
                                            const float* U, int kh0) {
    for (int idx = threadIdx.x; idx < 512 * 16; idx += SCAN_THREADS) {
        int k = idx >> 4;
        int c = idx & 15;
        int gate = c >> 2;
        int u4   = (c & 3) << 2;
        const float* src = (k < 256) ? (W + (size_t)k * 1024)
                                     : (U + (size_t)(k - 256) * 1024);
        float4 v = *(const float4*)(src + gate * 256 + kh0 + u4);
        *(float4*)(Wsm + k * 64 + gate * 16 + u4) = v;
    }
}

// Half-block weight load: 256 rows from src into Wsm rows [rowbase, rowbase+256).
__device__ __forceinline__ void load_w_half(float* Wsm, const float* src,
                                            int kh0, int rowbase, int ltid) {
    for (int idx = ltid; idx < 256 * 16; idx += 128) {
        int k = idx >> 4;
        int c = idx & 15;
        int gate = c >> 2;
        int u4   = (c & 3) << 2;
        float4 v = *(const float4*)(src + (size_t)k * 1024 + gate * 256 + kh0 + u4);
        *(float4*)(Wsm + (size_t)(rowbase + k) * 64 + gate * 16 + u4) = v;
    }
}

// 128-thread staging of a 16x256 tile (L1 bypass: data produced by other SMs).
__device__ __forceinline__ void stage_half(float* dst, const float* src, int ltid) {
    for (int idx = ltid; idx < BB * (HID / 2); idx += 128) {
        int r  = idx >> 7;
        int c2 = idx & 127;
        float2 v = __ldcg(((const float2*)(src + r * HID)) + c2);
        ((float2*)(dst + r * APITCH))[c2] = v;
    }
}

__device__ __forceinline__ void zero_tile(float* dst) {
    for (int idx = threadIdx.x; idx < BB * (HID / 2); idx += SCAN_THREADS) {
        int r  = idx >> 7;
        int c2 = idx & 127;
        ((float2*)(dst + r * APITCH))[c2] = make_float2(0.f, 0.f);
    }
}

// ---------------- K=64 chunk matmul (identical structure/order to R10) ----------------
// Apane already offset by the warp's K chunk; lane owns rows {rg+4q},
// col quads {4cg..+3, 32+4cg..+3}.
__device__ __forceinline__ void mm_chunk(const float* Apane, const float* wbase,
                                         float* gout, int rg, int cg) {
    const float* ar0 = Apane + (rg     ) * APITCH;
    const float* ar1 = Apane + (rg +  4) * APITCH;
    const float* ar2 = Apane + (rg +  8) * APITCH;
    const float* ar3 = Apane + (rg + 12) * APITCH;
    ull acc[4][4];
    #pragma unroll
    for (int q = 0; q < 4; ++q)
        #pragma unroll
        for (int j = 0; j < 4; ++j)
            acc[q][j] = 0ull;

    #pragma unroll 4
    for (int kk4 = 0; kk4 < 16; ++kk4) {
        float4 av0 = *(const float4*)(ar0 + kk4 * 4);
        float4 av1 = *(const float4*)(ar1 + kk4 * 4);
        float4 av2 = *(const float4*)(ar2 + kk4 * 4);
        float4 av3 = *(const float4*)(ar3 + kk4 * 4);
        #pragma unroll
        for (int s = 0; s < 4; ++s) {
            const float* wr = wbase + (kk4 * 4 + s) * 64;
            ulonglong2 wA = *(const ulonglong2*)(wr);       // cols 4cg..+3
            ulonglong2 wB = *(const ulonglong2*)(wr + 32);  // cols 32+4cg..+3
            float f0 = (s == 0) ? av0.x : (s == 1) ? av0.y : (s == 2) ? av0.z : av0.w;
            float f1 = (s == 0) ? av1.x : (s == 1) ? av1.y : (s == 2) ? av1.z : av1.w;
            float f2 = (s == 0) ? av2.x : (s == 1) ? av2.y : (s == 2) ? av2.z : av2.w;
            float f3 = (s == 0) ? av3.x : (s == 1) ? av3.y : (s == 2) ? av3.z : av3.w;
            ull v;
            v = pack2(f0);
            acc[0][0] = fma2(v, wA.x, acc[0][0]);
            acc[0][1] = fma2(v, wA.y, acc[0][1]);
            acc[0][2] = fma2(v, wB.x, acc[0][2]);
            acc[0][3] = fma2(v, wB.y, acc[0][3]);
            v = pack2(f1);
            acc[1][0] = fma2(v, wA.x, acc[1][0]);
            acc[1][1] = fma2(v, wA.y, acc[1][1]);
            acc[1][2] = fma2(v, wB.x, acc[1][2]);
            acc[1][3] = fma2(v, wB.y, acc[1][3]);
            v = pack2(f2);
            acc[2][0] = fma2(v, wA.x, acc[2][0]);
            acc[2][1] = fma2(v, wA.y, acc[2][1]);
            acc[2][2] = fma2(v, wB.x, acc[2][2]);
            acc[2][3] = fma2(v, wB.y, acc[2][3]);
            v = pack2(f3);
            acc[3][0] = fma2(v, wA.x, acc[3][0]);
            acc[3][1] = fma2(v, wA.y, acc[3][1]);
            acc[3][2] = fma2(v, wB.x, acc[3][2]);
            acc[3][3] = fma2(v, wB.y, acc[3][3]);
        }
    }

    #pragma unroll
    for (int q = 0; q < 4; ++q) {
        float* orow = gout + (rg + 4 * q) * GPAD;
        *(ulonglong2*)(orow + 4 * cg)      = make_ulonglong2(acc[q][0], acc[q][1]);
        *(ulonglong2*)(orow + 32 + 4 * cg) = make_ulonglong2(acc[q][2], acc[q][3]);
    }
}

// ---------------- persistent 12-layer LSTM scan, warp-specialized pipeline ----------------
// Block (bx, by): hidden units [bx*16,+16), batch rows [by*16,+16).
// Warps 0-3 (x-warps): x@W partials + x staging — never touch the grid barrier.
// Warps 4-7 (h-warps): h@U partials + barrier + h staging.
// Per iteration t:  [h-warps: h_t@U | x-warps: stage x_{t+1}]  syncA
//                   gates_t (all)                              syncB
//                   [x-warps: x_{t+1}@W | h-warps: barrier + stage h_{t+1}]
__global__ void __launch_bounds__(SCAN_THREADS, 1)
scan_all_kernel(const float* __restrict__ W0, const float* __restrict__ U0,
                const float* __restrict__ b0,
                const float* __restrict__ Ws, const float* __restrict__ Us,
                const float* __restrict__ bs)
{
    extern __shared__ float sm[];
    float* Wsm = sm + SM_W;
    float* xsm = sm + SM_X;
    float* hsm = sm + SM_H;
    float* gsm = sm + SM_G;

    const int tid = threadIdx.x;
    const int kh0 = blockIdx.x * UB;   // first hidden unit owned
    const int by  = blockIdx.y;
    const int b0r = by * BB;           // first batch row owned
    unsigned* cnt = &g_cnt[by][0];

    // ---- gate-phase mapping ----
    const int gr = tid >> 4;          // local batch row 0..15
    const int gu = tid & 15;          // local hidden unit 0..15
    const int hb = b0r + gr;
    const int hu = kh0 + gu;
    float creg = 0.0f;                // cell state in a register for all 12 layers
    float bi = b0[hu];
    float bf = b0[256 + hu];
    float bg = b0[512 + hu];
    float bo = b0[768 + hu];

    // ---- matmul mapping ----
    const int  w    = tid >> 5;          // 0..7
    const int  ln   = tid & 31;
    const int  rg   = ln >> 3;
    const int  cg   = ln & 7;
    const bool is_x = (w < 4);
    const float* Apane = (is_x ? xsm : hsm) + (w & 3) * 64;   // warp's K chunk
    const float* wbase = Wsm + (size_t)(w * 64) * 64 + 4 * cg;
    float*       gout  = gsm + w * (BB * GPAD);
    const int    ltid  = tid & 127;      // index within half

    const float* xin  = g_seq[0];
    float*       yout = g_seq[1];

    // ---- prologue: layer-0 weights, x_0, h_0 = 0, then x_0@W -> gsmX ----
    load_wslice(Wsm, W0, U0, kh0);
    stage_half(xsm, xin + (size_t)b0r * HID, ltid);   // both halves stage (idempotent)
    zero_tile(hsm);
    __syncthreads();
    if (is_x) mm_chunk(Apane, wbase, gout, rg, cg);

    unsigned barn = 0;                 // barriers completed in this by-group

    for (int l = 0; l < NLAYERS; ++l) {
        for (int t = 0; t < SEQ; ++t) {
            // ---- phase 1: h-warps h_t@U; x-warps stage next x ----
            if (!is_x) {
                mm_chunk(Apane, wbase, gout, rg, cg);
            } else {
                const float* xsrc = (t < SEQ - 1)
                    ? xin + ((size_t)(t + 1) * BATCH + b0r) * HID   // x_{t+1}
                    : yout + (size_t)b0r * HID;                     // next layer's x_0
                stage_half(xsm, xsrc, ltid);
            }
            __syncthreads();   // (A) gsmX (prev iter) + gsmH + xsm ready

            // ---- phase 2: gates + state update (all threads) ----
            {
                float s0 = bi, s1 = bf, s2 = bg, s3 = bo;
                #pragma unroll
                for (int ww = 0; ww < 8; ++ww) {
                    const float* gp = gsm + ww * (BB * GPAD) + gr * GPAD;
                    s0 += gp[gu];
                    s1 += gp[16 + gu];
                    s2 += gp[32 + gu];
                    s3 += gp[48 + gu];
                }
                float ct = sigf(s1) * creg + sigf(s0) * tanh_sig(s2);
                float hv = sigf(s3) * tanh_sig(ct);
                creg = ct;
                __stcg(&g_h[(t + 1) & 1][hb][hu], hv);           // by-group broadcast (L2)
                yout[((size_t)t * BATCH + hb) * HID + hu] = hv;  // layer output sequence
            }

            if (l == NLAYERS - 1 && t == SEQ - 1) break;

            __syncthreads();   // (B) gsm consumed; h stores issued block-wide
            ++barn;
            const unsigned tgt = barn * NSYNC;
            const bool reload = (t == SEQ - 1) && (l == 0);
            if (reload) {                      // switch to shared-layer biases
                bi = bs[hu];
                bf = bs[256 + hu];
                bg = bs[512 + hu];
                bo = bs[768 + hu];
            }

            // ---- phase 3: specialized ----
            if (is_x) {
                if (reload) {                  // new W half for layers 1..11
                    load_w_half(Wsm, Ws, kh0, 0, ltid);
                    bar_named(2);              // x-warps-only: W visible to all 4
                }
                mm_chunk(Apane, wbase, gout, rg, cg);   // x_{t+1}@W -> gsmX
            } else {
                if (tid == 128) bar_arrive(cnt);        // release h stores
                if (reload)                    // new U half (overlaps barrier wait)
                    load_w_half(Wsm, Us, kh0, 256, ltid);
                if (tid == 128) {
                    while (ld_acq(cnt) < tgt) { }       // single poller per block
                }
                bar_named(1);                  // h-warps: barrier released
                stage_half(hsm, &g_h[(t + 1) & 1][b0r][0], ltid);
                bar_named(1);                  // hsm visible to all 4 h-warps
            }
        }
        // swap sequence buffers for next layer
        const float* tx = xin;
        xin  = yout;
        yout = (float*)tx;
    }
}

// ---------------- final FC: out[b][o] = h_final[b] . fcW[:,o] + fcb[o] ----------------
__global__ void fc_kernel(const float* __restrict__ fcW,
                          const float* __restrict__ fcb,
                          float* __restrict__ out)
{
    int idx = blockIdx.x * blockDim.x + threadIdx.x;
    if (idx >= BATCH * NOUT) return;
    int b = idx / NOUT;
    int o = idx - b * NOUT;
    float acc = fcb[o];
    const float* hrow = &g_h[0][b][0];   // t=255 writes parity (255+1)&1 = buf 0
    #pragma unroll 8
    for (int k = 0; k < HID; ++k)
        acc = fmaf(hrow[k], fcW[k * NOUT + o], acc);
    out[idx] = acc;
}

// ---------------- launch ----------------
extern "C" void kernel_launch(void* const* d_in, const int* in_sizes, int n_in,
                              void* d_out, int out_size)
{
    const int*   x   = (const int*)  d_in[0];
    const float* tab = (const float*)d_in[1];
    const float* W0  = (const float*)d_in[2];
    const float* U0  = (const float*)d_in[3];
    const float* b0  = (const float*)d_in[4];
    const float* Ws  = (const float*)d_in[5];
    const float* Us  = (const float*)d_in[6];
    const float* bs  = (const float*)d_in[7];
    const float* fcW = (const float*)d_in[8];
    const float* fcb = (const float*)d_in[9];
    float* out = (float*)d_out;

    cudaFuncSetAttribute(scan_all_kernel,
                         cudaFuncAttributeMaxDynamicSharedMemorySize,
                         SM_TOT * (int)sizeof(float));

    init_state_kernel<<<1, 32>>>();     // reset barrier counters per replay

    embed_kernel<<<(BATCH * SEQ * (HID / 4) + 255) / 256, 256>>>(x, tab);

    scan_all_kernel<<<dim3(16, 8), SCAN_THREADS, SM_TOT * (int)sizeof(float)>>>(
        W0, U0, b0, Ws, Us, bs);

    fc_kernel<<<(BATCH * NOUT + 255) / 256, 256>>>(fcW, fcb, out);

    (void)in_sizes; (void)n_in; (void)out_size;
}

// round 12
// speedup vs baseline: 1.5293x; 1.0061x over previous
#include <cuda_runtime.h>

// ---------------- problem constants ----------------
#define SEQ     256
#define BATCH   128
#define HID     256
#define NLAYERS 12
#define NOUT    10

// scan geometry: 128 blocks = 16 unit-groups x 8 batch-groups, persistent
#define SCAN_THREADS 256
#define BB           16            // batch rows per block
#define UB           16            // hidden units per block (=> 64 gate cols)
#define NSYNC        16            // blocks per barrier group (one per by)
#define APITCH       260           // x/h tile row pitch (floats, 16B-aligned rows)
#define GPAD         68            // partial-buffer row pitch (16B-aligned)
#define GTILE        (BB*GPAD)     // one 16x64 partial tile (padded)

// smem layout (float offsets)
#define SM_W    0                          // fused W|U slice [512][64]
#define SM_X    (SM_W + 512*64)            // x tile [16][260]
#define SM_H    (SM_X + BB*APITCH)         // h tile [16][260]
#define SM_GH   (SM_H + BB*APITCH)         // 4 h-partial tiles
#define SM_GX0  (SM_GH + 4*GTILE)          // 4 x-partial tiles, buffer 0
#define SM_GX1  (SM_GX0 + 4*GTILE)         // 4 x-partial tiles, buffer 1
#define SM_TOT  (SM_GX1 + 4*GTILE)         // 54144 floats = 216576 bytes

typedef unsigned long long ull;

// ---------------- device scratch (no allocations allowed) ----------------
__device__ float    g_seq[2][(size_t)SEQ * BATCH * HID]; // ping-pong layer sequences
__device__ float    g_h[2][BATCH][HID];                  // ping-pong hidden state
__device__ unsigned g_cnt[8][128];                       // per-by barrier counters (512B apart)

// ---------------- packed f32x2 + barrier helpers ----------------
__device__ __forceinline__ ull fma2(ull a, ull b, ull c) {
    ull d;
    asm("fma.rn.f32x2 %0, %1, %2, %3;" : "=l"(d) : "l"(a), "l"(b), "l"(c));
    return d;
}
__device__ __forceinline__ ull pack2(float v) {
    ull d;
    asm("mov.b64 %0, {%1, %1};" : "=l"(d) : "f"(v));
    return d;
}
__device__ __forceinline__ void bar_arrive(unsigned* p) {
    asm volatile("red.release.gpu.add.u32 [%0], %1;" :: "l"(p), "r"(1u) : "memory");
}
__device__ __forceinline__ unsigned ld_acq(const unsigned* p) {
    unsigned v;
    asm volatile("ld.acquire.gpu.u32 %0, [%1];" : "=r"(v) : "l"(p) : "memory");
    return v;
}
__device__ __forceinline__ void bar_named(int id) {       // 128-thread named barrier
    asm volatile("bar.sync %0, 128;" :: "r"(id) : "memory");
}
__device__ __forceinline__ void barB_arrive() {           // x-warps: non-blocking
    asm volatile("bar.arrive 3, 256;" ::: "memory");
}
__device__ __forceinline__ void barB_sync() {             // h-warps: wait x arrivals
    asm volatile("bar.sync 3, 256;" ::: "memory");
}

// ---------------- math helpers ----------------
__device__ __forceinline__ float sigf(float x) {
    return 1.0f / (1.0f + __expf(-x));
}
__device__ __forceinline__ float tanh_sig(float x) {
    return fmaf(2.0f, sigf(2.0f * x), -1.0f);   // tanh(x) = 2*sigmoid(2x) - 1
}

// ---------------- init: reset barrier counters (deterministic per replay) ----------------
__global__ void init_state_kernel() {
    int i = threadIdx.x;
    if (i < 8) g_cnt[i][0] = 0u;
}

// ---------------- embedding gather -> g_seq[0] laid out [s][b][e] ----------------
__global__ void embed_kernel(const int* __restrict__ x, const float* __restrict__ tab) {
    int idx = blockIdx.x * blockDim.x + threadIdx.x;     // over S*B*64 float4 chunks
    if (idx >= BATCH * SEQ * (HID / 4)) return;
    int e4 = idx & 63;
    int sb = idx >> 6;            // s*BATCH + b
    int b  = sb & (BATCH - 1);
    int s  = sb >> 7;
    int tok = x[b * SEQ + s];
    float4 v = *(const float4*)(tab + (size_t)tok * HID + e4 * 4);
    *(float4*)(&g_seq[0][(size_t)sb * HID + e4 * 4]) = v;
}

// ---------------- cooperative helpers ----------------
// Full-block weight slice load (prologue): fused [512 rows][64 gate cols].
__device__ __forceinline__ void load_wslice(float* Wsm, const float* W,
                                            const float* U, int kh0) {
    for (int idx = threadIdx.x; idx < 512 * 16; idx += SCAN_THREADS) {
        int k = idx >> 4;
        int c = idx & 15;
        int gate = c >> 2;
        int u4   = (c & 3) << 2;
        const float* src = (k < 256) ? (W + (size_t)k * 1024)
                                     : (U + (size_t)(k - 256) * 1024);
        float4 v = *(const float4*)(src + gate * 256 + kh0 + u4);
        *(float4*)(Wsm + k * 64 + gate * 16 + u4) = v;
    }
}

// Half-block weight load: 256 rows from src into Wsm rows [rowbase, rowbase+256).
__device__ __forceinline__ void load_w_half(float* Wsm, const float* src,
                                            int kh0, int rowbase, int ltid) {
    for (int idx = ltid; idx < 256 * 16; idx += 128) {
        int k = idx >> 4;
        int c = idx & 15;
        int gate = c >> 2;
        int u4   = (c & 3) << 2;
        float4 v = *(const float4*)(src + (size_t)k * 1024 + gate * 256 + kh0 + u4);
        *(float4*)(Wsm + (size_t)(rowbase + k) * 64 + gate * 16 + u4) = v;
    }
}

// 128-thread staging of a 16x256 tile (L1 bypass: data produced by other SMs).
__device__ __forceinline__ void stage_half(float* dst, const float* src, int ltid) {
    for (int idx = ltid; idx < BB * (HID / 2); idx += 128) {
        int r  = idx >> 7;
        int c2 = idx & 127;
        float2 v = __ldcg(((const float2*)(src + r * HID)) + c2);
        ((float2*)(dst + r * APITCH))[c2] = v;
    }
}

__device__ __forceinline__ void zero_tile(float* dst) {
    for (int idx = threadIdx.x; idx < BB * (HID / 2); idx += SCAN_THREADS) {
        int r  = idx >> 7;
        int c2 = idx & 127;
        ((float2*)(dst + r * APITCH))[c2] = make_float2(0.f, 0.f);
    }
}

// ---------------- K=64 chunk matmul (identical math/order to R11) ----------------
// Apane already offset by the warp's K chunk; lane owns rows {rg+4q},
// col quads {4cg..+3, 32+4cg..+3}.
__device__ __forceinline__ void mm_chunk(const float* Apane, const float* wbase,
                                         float* gout, int rg, int cg) {
    const float* ar0 = Apane + (rg     ) * APITCH;
    const float* ar1 = Apane + (rg +  4) * APITCH;
    const float* ar2 = Apane + (rg +  8) * APITCH;
    const float* ar3 = Apane + (rg + 12) * APITCH;
    ull acc[4][4];
    #pragma unroll
    for (int q = 0; q < 4; ++q)
        #pragma unroll
        for (int j = 0; j < 4; ++j)
            acc[q][j] = 0ull;

    #pragma unroll 4
    for (int kk4 = 0; kk4 < 16; ++kk4) {
        float4 av0 = *(const float4*)(ar0 + kk4 * 4);
        float4 av1 = *(const float4*)(ar1 + kk4 * 4);
        float4 av2 = *(const float4*)(ar2 + kk4 * 4);
        float4 av3 = *(const float4*)(ar3 + kk4 * 4);
        #pragma unroll
        for (int s = 0; s < 4; ++s) {
            const float* wr = wbase + (kk4 * 4 + s) * 64;
            ulonglong2 wA = *(const ulonglong2*)(wr);       // cols 4cg..+3
            ulonglong2 wB = *(const ulonglong2*)(wr + 32);  // cols 32+4cg..+3
            float f0 = (s == 0) ? av0.x : (s == 1) ? av0.y : (s == 2) ? av0.z : av0.w;
            float f1 = (s == 0) ? av1.x : (s == 1) ? av1.y : (s == 2) ? av1.z : av1.w;
            float f2 = (s == 0) ? av2.x : (s == 1) ? av2.y : (s == 2) ? av2.z : av2.w;
            float f3 = (s == 0) ? av3.x : (s == 1) ? av3.y : (s == 2) ? av3.z : av3.w;
            ull v;
            v = pack2(f0);
            acc[0][0] = fma2(v, wA.x, acc[0][0]);
            acc[0][1] = fma2(v, wA.y, acc[0][1]);
            acc[0][2] = fma2(v, wB.x, acc[0][2]);
            acc[0][3] = fma2(v, wB.y, acc[0][3]);
            v = pack2(f1);
            acc[1][0] = fma2(v, wA.x, acc[1][0]);
            acc[1][1] = fma2(v, wA.y, acc[1][1]);
            acc[1][2] = fma2(v, wB.x, acc[1][2]);
            acc[1][3] = fma2(v, wB.y, acc[1][3]);
            v = pack2(f2);
            acc[2][0] = fma2(v, wA.x, acc[2][0]);
            acc[2][1] = fma2(v, wA.y, acc[2][1]);
            acc[2][2] = fma2(v, wB.x, acc[2][2]);
            acc[2][3] = fma2(v, wB.y, acc[2][3]);
            v = pack2(f3);
            acc[3][0] = fma2(v, wA.x, acc[3][0]);
            acc[3][1] = fma2(v, wA.y, acc[3][1]);
            acc[3][2] = fma2(v, wB.x, acc[3][2]);
            acc[3][3] = fma2(v, wB.y, acc[3][3]);
        }
    }

    #pragma unroll
    for (int q = 0; q < 4; ++q) {
        float* orow = gout + (rg + 4 * q) * GPAD;
        *(ulonglong2*)(orow + 4 * cg)      = make_ulonglong2(acc[q][0], acc[q][1]);
        *(ulonglong2*)(orow + 32 + 4 * cg) = make_ulonglong2(acc[q][2], acc[q][3]);
    }
}

// ---------------- persistent 12-layer LSTM scan, decoupled warp pipeline ----------------
// Block (bx, by): hidden units [bx*16,+16), batch rows [by*16,+16).
// Per iteration t:
//   phase1: [h-warps: h_t@U -> gsmH | x-warps: stage x_{t+1}]     __syncthreads (A)
//   gates_t (all threads; reads gsmX[t&1] + gsmH)
//   split:  x-warps bar.arrive(3) -> x_{t+1}@W -> gsmX[(t+1)&1]   (never blocks)
//           h-warps bar.sync(3) -> grid arrive/poll -> stage h_{t+1}
// gsmX double-buffered so x-warps can write without waiting for gates readers.
__global__ void __launch_bounds__(SCAN_THREADS, 1)
scan_all_kernel(const float* __restrict__ W0, const float* __restrict__ U0,
                const float* __restrict__ b0,
                const float* __restrict__ Ws, const float* __restrict__ Us,
                const float* __restrict__ bs)
{
    extern __shared__ float sm[];
    float* Wsm   = sm + SM_W;
    float* xsm   = sm + SM_X;
    float* hsm   = sm + SM_H;
    float* gsmH  = sm + SM_GH;
    float* gsmX0 = sm + SM_GX0;
    float* gsmX1 = sm + SM_GX1;

    const int tid = threadIdx.x;
    const int kh0 = blockIdx.x * UB;   // first hidden unit owned
    const int by  = blockIdx.y;
    const int b0r = by * BB;           // first batch row owned
    unsigned* cnt = &g_cnt[by][0];

    // ---- gate-phase mapping ----
    const int gr = tid >> 4;          // local batch row 0..15
    const int gu = tid & 15;          // local hidden unit 0..15
    const int hb = b0r + gr;
    const int hu = kh0 + gu;
    float creg = 0.0f;                // cell state in a register for all 12 layers
    float bi = b0[hu];
    float bf = b0[256 + hu];
    float bg = b0[512 + hu];
    float bo = b0[768 + hu];

    // ---- matmul mapping ----
    const int  w    = tid >> 5;          // 0..7
    const int  ln   = tid & 31;
    const int  rg   = ln >> 3;
    const int  cg   = ln & 7;
    const bool is_x = (w < 4);
    const float* Apane = (is_x ? xsm : hsm) + (w & 3) * 64;   // warp's K chunk
    const float* wbase = Wsm + (size_t)(w * 64) * 64 + 4 * cg;
    float* goutH  = gsmH  + (w & 3) * GTILE;   // h-warps' tile
    float* goutX0 = gsmX0 + (w & 3) * GTILE;   // x-warps' tiles (double-buffered)
    float* goutX1 = gsmX1 + (w & 3) * GTILE;
    const int ltid = tid & 127;          // index within half

    const float* xin  = g_seq[0];
    float*       yout = g_seq[1];

    // ---- prologue: layer-0 weights, x_0, h_0 = 0, then x_0@W -> gsmX0 ----
    load_wslice(Wsm, W0, U0, kh0);
    stage_half(xsm, xin + (size_t)b0r * HID, ltid);   // both halves stage (idempotent)
    zero_tile(hsm);
    __syncthreads();
    if (is_x) mm_chunk(Apane, wbase, goutX0, rg, cg);

    unsigned barn = 0;                 // barriers completed in this by-group

    for (int l = 0; l < NLAYERS; ++l) {
        for (int t = 0; t < SEQ; ++t) {
            // ---- phase 1: h-warps h_t@U; x-warps stage next x ----
            if (!is_x) {
                mm_chunk(Apane, wbase, goutH, rg, cg);
            } else {
                const float* xsrc = (t < SEQ - 1)
                    ? xin + ((size_t)(t + 1) * BATCH + b0r) * HID   // x_{t+1}
                    : yout + (size_t)b0r * HID;                     // next layer's x_0
                stage_half(xsm, xsrc, ltid);
            }
            __syncthreads();   // (A) gsmX[t&1] (prev split) + gsmH + xsm ready

            // ---- phase 2: gates + state update (all threads) ----
            {
                const float* gx = (t & 1) ? gsmX1 : gsmX0;
                float s0 = bi, s1 = bf, s2 = bg, s3 = bo;
                #pragma unroll
                for (int ww = 0; ww < 4; ++ww) {           // x partials (tiles 0-3)
                    const float* gp = gx + ww * GTILE + gr * GPAD;
                    s0 += gp[gu];
                    s1 += gp[16 + gu];
                    s2 += gp[32 + gu];
                    s3 += gp[48 + gu];
                }
                #pragma unroll
                for (int ww = 0; ww < 4; ++ww) {           // h partials (tiles 4-7)
                    const float* gp = gsmH + ww * GTILE + gr * GPAD;
                    s0 += gp[gu];
                    s1 += gp[16 + gu];
                    s2 += gp[32 + gu];
                    s3 += gp[48 + gu];
                }
                float ct = sigf(s1) * creg + sigf(s0) * tanh_sig(s2);
                float hv = sigf(s3) * tanh_sig(ct);
                creg = ct;
                __stcg(&g_h[(t + 1) & 1][hb][hu], hv);           // by-group broadcast (L2)
                yout[((size_t)t * BATCH + hb) * HID + hu] = hv;  // layer output sequence
            }

            if (l == NLAYERS - 1 && t == SEQ - 1) break;

            ++barn;
            const unsigned tgt = barn * NSYNC;
            const bool reload = (t == SEQ - 1) && (l == 0);
            if (reload) {                      // switch to shared-layer biases
                bi = bs[hu];
                bf = bs[256 + hu];
                bg = bs[512 + hu];
                bo = bs[768 + hu];
            }

            // ---- phase 3: decoupled split ----
            if (is_x) {
                barB_arrive();                 // non-blocking: signal gates done
                if (reload) {                  // new W half for layers 1..11
                    load_w_half(Wsm, Ws, kh0, 0, ltid);
                    bar_named(2);              // x-warps-only: W visible to all 4
                }
                // x_{t+1}@W into the buffer gates(t+1) will read
                mm_chunk(Apane, wbase, ((t + 1) & 1) ? goutX1 : goutX0, rg, cg);
            } else {
                barB_sync();                   // wait x-warps' gates stores
                if (tid == 128) bar_arrive(cnt);        // release block's h stores
                if (reload)                    // new U half (overlaps barrier wait)
                    load_w_half(Wsm, Us, kh0, 256, ltid);
                if (tid == 128) {
                    while (ld_acq(cnt) < tgt) { }       // single poller per block
                }
                bar_named(1);                  // h-warps: barrier released
                stage_half(hsm, &g_h[(t + 1) & 1][b0r][0], ltid);
                bar_named(1);                  // hsm visible to all 4 h-warps
            }
        }
        // swap sequence buffers for next layer
        const float* tx = xin;
        xin  = yout;
        yout = (float*)tx;
    }
}

// ---------------- final FC: one warp per batch row ----------------
__global__ void fc_kernel(const float* __restrict__ fcW,
                          const float* __restrict__ fcb,
                          float* __restrict__ out)
{
    int b  = blockIdx.x;        // 128 blocks
    int ln = threadIdx.x;       // 32 threads
    float acc[NOUT];
    #pragma unroll
    for (int o = 0; o < NOUT; ++o) acc[o] = 0.0f;

    const float* hrow = &g_h[0][b][0];   // t=255 writes parity (255+1)&1 = buf 0
    #pragma unroll
    for (int k = ln; k < HID; k += 32) {
        float hv = __ldcg(hrow + k);
        const float* wr = fcW + k * NOUT;
        #pragma unroll
        for (int o = 0; o < NOUT; ++o)
            acc[o] = fmaf(hv, wr[o], acc[o]);
    }
    #pragma unroll
    for (int off = 16; off > 0; off >>= 1)
        #pragma unroll
        for (int o = 0; o < NOUT; ++o)
            acc[o] += __shfl_down_sync(0xffffffffu, acc[o], off);
    if (ln == 0) {
        #pragma unroll
        for (int o = 0; o < NOUT; ++o)
            out[b * NOUT + o] = acc[o] + fcb[o];
    }
}

// ---------------- launch ----------------
extern "C" void kernel_launch(void* const* d_in, const int* in_sizes, int n_in,
                              void* d_out, int out_size)
{
    const int*   x   = (const int*)  d_in[0];
    const float* tab = (const float*)d_in[1];
    const float* W0  = (const float*)d_in[2];
    const float* U0  = (const float*)d_in[3];
    const float* b0  = (const float*)d_in[4];
    const float* Ws  = (const float*)d_in[5];
    const float* Us  = (const float*)d_in[6];
    const float* bs  = (const float*)d_in[7];
    const float* fcW = (const float*)d_in[8];
    const float* fcb = (const float*)d_in[9];
    float* out = (float*)d_out;

    cudaFuncSetAttribute(scan_all_kernel,
                         cudaFuncAttributeMaxDynamicSharedMemorySize,
                         SM_TOT * (int)sizeof(float));

    init_state_kernel<<<1, 32>>>();     // reset barrier counters per replay

    embed_kernel<<<(BATCH * SEQ * (HID / 4) + 255) / 256, 256>>>(x, tab);

    scan_all_kernel<<<dim3(16, 8), SCAN_THREADS, SM_TOT * (int)sizeof(float)>>>(
        W0, U0, b0, Ws, Us, bs);

    fc_kernel<<<BATCH, 32>>>(fcW, fcb, out);

    (void)in_sizes; (void)n_in; (void)out_size;
}